// round 3
// baseline (speedup 1.0000x reference)
#include <cuda_runtime.h>

#define TV 12800          // T*V = 256*50
#define CTV 819200        // C*TV = 64*12800

// Scratch (allocation-free rule: __device__ globals)
__device__ float g_q[26214400];            // [32][64][256][50]
__device__ float g_k[26214400];
__device__ float g_v[26214400];
__device__ float g_attn[32 * 8 * 50 * 50]; // [n][h][u][v]
__device__ float g_G[209715200];           // [n][h][o][t][u]  (839 MB)

// ---------------------------------------------------------------------------
// proj_kernel: Y[b][o][m] = sum_c W[o][c] * X[b][c][m] (+bias)
// mode 0/1/2: q/k/v projection, b = n (gridDim.y = 32), W 64x64 stride 64
// mode 3:     G = o_w_h @ v,   b = n*8+h (gridDim.y = 256), W stride 512, col off h*64
// Block: 128-wide m tile, all 64 output rows. 256 thr, 8x4 micro-tile.
// ---------------------------------------------------------------------------
__global__ __launch_bounds__(256) void proj_kernel(const float* __restrict__ Xin,
                                                   const float* __restrict__ W,
                                                   const float* __restrict__ bias,
                                                   int mode)
{
    __shared__ float Ws[64 * 64];                 // [o][c]
    __shared__ __align__(16) float Xs[64 * 128];  // [c][m]
    const int b   = blockIdx.y;
    const int m0  = blockIdx.x * 128;
    const int tid = threadIdx.x;

    const float* Xb;
    const float* Wb;
    float* Yb;
    int wStride;
    if (mode == 3) {
        Xb = g_v + (size_t)(b >> 3) * CTV;
        Wb = W + (b & 7) * 64;
        wStride = 512;
        Yb = g_G + (size_t)b * CTV;
    } else {
        Xb = Xin + (size_t)b * CTV;
        Wb = W;
        wStride = 64;
        Yb = (mode == 0 ? g_q : (mode == 1 ? g_k : g_v)) + (size_t)b * CTV;
    }

    for (int idx = tid; idx < 4096; idx += 256) {
        int o = idx >> 6, c = idx & 63;
        Ws[idx] = Wb[o * wStride + c];
    }
    for (int idx = tid; idx < 2048; idx += 256) {  // float4 granules
        int c = idx >> 5, col = (idx & 31) << 2;
        *(float4*)&Xs[c * 128 + col] =
            *(const float4*)&Xb[(size_t)c * TV + m0 + col];
    }
    __syncthreads();

    const int to = tid >> 5;          // o rows: to*8 .. to*8+7 (per-warp uniform)
    const int tm = (tid & 31) << 2;   // m cols: tm .. tm+3

    float acc[8][4];
#pragma unroll
    for (int i = 0; i < 8; i++)
#pragma unroll
        for (int j = 0; j < 4; j++) acc[i][j] = 0.f;

#pragma unroll 4
    for (int c = 0; c < 64; c++) {
        float4 x = *(const float4*)&Xs[c * 128 + tm];
#pragma unroll
        for (int i = 0; i < 8; i++) {
            float w = Ws[(to * 8 + i) * 64 + c];  // warp-broadcast LDS
            acc[i][0] = fmaf(w, x.x, acc[i][0]);
            acc[i][1] = fmaf(w, x.y, acc[i][1]);
            acc[i][2] = fmaf(w, x.z, acc[i][2]);
            acc[i][3] = fmaf(w, x.w, acc[i][3]);
        }
    }

#pragma unroll
    for (int i = 0; i < 8; i++) {
        int o = to * 8 + i;
        float bv = bias ? bias[o] : 0.0f;
        float4 r;
        r.x = acc[i][0] + bv; r.y = acc[i][1] + bv;
        r.z = acc[i][2] + bv; r.w = acc[i][3] + bv;
        *(float4*)&Yb[(size_t)o * TV + m0 + tm] = r;
    }
}

// ---------------------------------------------------------------------------
// attn_kernel: per (n,h): scores[u][v] = sum_{r<2048} Q[r][u]*K[r][v] / 2048
//              attn = tanh(scores)*alpha[h] + global_attn[u][v]
// The (hc=8, T=256) contraction dims are one contiguous [2048][50] chunk.
// ---------------------------------------------------------------------------
__global__ __launch_bounds__(256) void attn_kernel(const float* __restrict__ alphas,
                                                   const float* __restrict__ ga)
{
    __shared__ float Qs[1600];
    __shared__ float Ks[1600];
    const int nh = blockIdx.x;                    // n*8 + h
    const float* Q = g_q + (size_t)nh * 102400;   // (n*64 + h*8)*TV
    const float* K = g_k + (size_t)nh * 102400;
    const int tid = threadIdx.x;
    const bool active = tid < 250;
    const int v  = tid % 50;
    const int uq = tid / 50;                      // u = uq + 5*i

    float acc[10];
#pragma unroll
    for (int i = 0; i < 10; i++) acc[i] = 0.f;

    for (int kb = 0; kb < 2048; kb += 32) {
        for (int idx = tid; idx < 1600; idx += 256) {
            Qs[idx] = Q[kb * 50 + idx];
            Ks[idx] = K[kb * 50 + idx];
        }
        __syncthreads();
        if (active) {
#pragma unroll 4
            for (int r = 0; r < 32; r++) {
                float kv = Ks[r * 50 + v];
#pragma unroll
                for (int i = 0; i < 10; i++)
                    acc[i] = fmaf(Qs[r * 50 + uq + 5 * i], kv, acc[i]);
            }
        }
        __syncthreads();
    }

    if (active) {
        const float alpha = alphas[nh & 7];
        float* A = g_attn + (size_t)nh * 2500;
#pragma unroll
        for (int i = 0; i < 10; i++) {
            int u = uq + 5 * i;
            float s = acc[i] * (1.0f / 2048.0f);
            A[u * 50 + v] = tanhf(s) * alpha + ga[u * 50 + v];
        }
    }
}

// ---------------------------------------------------------------------------
// out_kernel: out[n][o][t][v] = sum_{h,u} G[n][h][o][t][u] * attn[n][h][u][v] + o_b[o]
// Block: (tb: 32-wide t tile, ob: 4-wide o tile, n). 128 rows x 50 cols (padded 64).
// 256 thr, 8x4 micro-tile, FFMA-bound inner loop (32 FMA vs ~11 LDS per u).
// ---------------------------------------------------------------------------
__global__ __launch_bounds__(256) void out_kernel(const float* __restrict__ o_b,
                                                  float* __restrict__ out)
{
    __shared__ __align__(16) float As[50 * 64];   // [u][v] padded to 64 cols
    __shared__ float Gs[128 * 50];                // [r=oo*32+tt][u]
    const int tb  = blockIdx.x;   // 0..7
    const int ob  = blockIdx.y;   // 0..15
    const int n   = blockIdx.z;   // 0..31
    const int tid = threadIdx.x;
    const int vg  = (tid & 15) << 2;  // col base (v = vg..vg+3, valid < 50)
    const int rg  = tid >> 4;         // rows rg*8 .. rg*8+7

    float acc[8][4];
#pragma unroll
    for (int i = 0; i < 8; i++)
#pragma unroll
        for (int j = 0; j < 4; j++) acc[i][j] = 0.f;

    for (int h = 0; h < 8; h++) {
        const float* A = g_attn + (size_t)(n * 8 + h) * 2500;
        for (int idx = tid; idx < 3200; idx += 256) {
            int u = idx >> 6, vv = idx & 63;
            As[idx] = (vv < 50) ? A[u * 50 + vv] : 0.f;
        }
        const float* Gb = g_G + (size_t)(n * 8 + h) * CTV
                        + (size_t)(ob * 4) * TV + tb * 1600;
        for (int idx = tid; idx < 6400; idx += 256) {
            int oo  = idx / 1600;
            int rem = idx - oo * 1600;
            Gs[idx] = Gb[(size_t)oo * TV + rem];   // Gs[r][u], r = oo*32 + tt
        }
        __syncthreads();

#pragma unroll 2
        for (int u = 0; u < 50; u++) {
            float4 a = *(const float4*)&As[u * 64 + vg];
#pragma unroll
            for (int i = 0; i < 8; i++) {
                float g = Gs[(rg * 8 + i) * 50 + u];
                acc[i][0] = fmaf(g, a.x, acc[i][0]);
                acc[i][1] = fmaf(g, a.y, acc[i][1]);
                acc[i][2] = fmaf(g, a.z, acc[i][2]);
                acc[i][3] = fmaf(g, a.w, acc[i][3]);
            }
        }
        __syncthreads();
    }

#pragma unroll
    for (int i = 0; i < 8; i++) {
        int r = rg * 8 + i;
        int o = ob * 4 + (r >> 5);
        int t = tb * 32 + (r & 31);
        float bv = o_b[o];
        float* op = out + ((size_t)(n * 64 + o) * 256 + t) * 50 + vg;
#pragma unroll
        for (int j = 0; j < 4; j++)
            if (vg + j < 50) op[j] = acc[i][j] + bv;
    }
}

// ---------------------------------------------------------------------------
extern "C" void kernel_launch(void* const* d_in, const int* in_sizes, int n_in,
                              void* d_out, int out_size)
{
    (void)in_sizes; (void)n_in; (void)out_size;
    const float* x_q    = (const float*)d_in[0];
    const float* x_kv   = (const float*)d_in[1];
    const float* q_w    = (const float*)d_in[2];
    const float* q_b    = (const float*)d_in[3];
    const float* k_w    = (const float*)d_in[4];
    const float* k_b    = (const float*)d_in[5];
    const float* v_w    = (const float*)d_in[6];
    const float* v_b    = (const float*)d_in[7];
    const float* o_w    = (const float*)d_in[8];
    const float* o_b    = (const float*)d_in[9];
    const float* alphas = (const float*)d_in[10];
    const float* ga     = (const float*)d_in[11];
    float* out = (float*)d_out;

    dim3 blk(256);
    proj_kernel<<<dim3(100, 32), blk>>>(x_q,  q_w, q_b, 0);   // q
    proj_kernel<<<dim3(100, 32), blk>>>(x_kv, k_w, k_b, 1);   // k
    proj_kernel<<<dim3(100, 32), blk>>>(x_kv, v_w, v_b, 2);   // v
    attn_kernel<<<256, blk>>>(alphas, ga);                    // scores -> attn
    proj_kernel<<<dim3(100, 256), blk>>>(nullptr, o_w, nullptr, 3);  // G = o_w_h @ v
    out_kernel<<<dim3(8, 16, 32), blk>>>(o_b, out);           // out = G x attn + bias
}

// round 4
// speedup vs baseline: 1.0192x; 1.0192x over previous
#include <cuda_runtime.h>

typedef unsigned long long ull;

// Packed 2-wide fp32 FMA (sm_100+ only; ptxas never auto-emits it)
#define FMA2(d, a, b) asm("fma.rn.f32x2 %0, %1, %2, %0;" : "+l"(d) : "l"(a), "l"(b))

__device__ __forceinline__ ull dup2(float w) {
    ull r; asm("mov.b64 %0, {%1, %1};" : "=l"(r) : "f"(w)); return r;
}
__device__ __forceinline__ float2 up2(ull v) {
    float2 r; asm("mov.b64 {%0, %1}, %2;" : "=f"(r.x), "=f"(r.y) : "l"(v)); return r;
}

#define TV 12800          // T*V = 256*50
#define CTV 819200        // C*TV

// Scratch (allocation-free rule: __device__ globals)
__device__ float g_q[26214400];          // [32][64][256][50]
__device__ float g_k[26214400];
__device__ float g_part[256 * 8 * 2500]; // split-K score partials
__device__ float g_attn[256 * 2500];     // [n*8+h][u][v]

// ---------------------------------------------------------------------------
// proj_qk: Y[b][o][m] = sum_c W[o][c] * X[b][c][m] + bias  (q and k fused via z)
// 256 thr; thread = og(8 rows of 8 o) x mg(32 m-pairs); FFMA2 over m-pairs.
// ---------------------------------------------------------------------------
__global__ __launch_bounds__(256) void proj_qk(const float* __restrict__ x_q,
                                               const float* __restrict__ q_w,
                                               const float* __restrict__ q_b,
                                               const float* __restrict__ x_k,
                                               const float* __restrict__ k_w,
                                               const float* __restrict__ k_b)
{
    extern __shared__ float psm[];
    float* Xs = psm;            // [64][128]
    float* Wd = psm + 8192;     // [c][o] transposed weights, 64*64

    const int n   = blockIdx.y;
    const int m0  = blockIdx.x * 128;
    const int qk  = blockIdx.z;
    const int tid = threadIdx.x;

    const float* X  = (qk ? x_k : x_q) + (size_t)n * CTV;
    const float* W  = qk ? k_w : q_w;
    const float* Bv = qk ? k_b : q_b;
    float* Y        = (qk ? g_k : g_q) + (size_t)n * CTV;

    for (int idx = tid; idx < 4096; idx += 256) {   // c consecutive: coalesced
        int c = idx & 63, o = idx >> 6;
        Wd[c * 64 + o] = W[o * 64 + c];
    }
    for (int idx = tid; idx < 2048; idx += 256) {
        int c = idx >> 5, col = (idx & 31) << 2;
        *(float4*)&Xs[c * 128 + col] = *(const float4*)&X[(size_t)c * TV + m0 + col];
    }
    __syncthreads();

    const int og = tid >> 5;       // o rows og*8..+7
    const int mg = tid & 31;       // m-pairs mg, mg+32

    ull acc[8][2];
#pragma unroll
    for (int i = 0; i < 8; i++) { acc[i][0] = 0ull; acc[i][1] = 0ull; }

#pragma unroll 4
    for (int c = 0; c < 64; c++) {
        const ull* xr = (const ull*)&Xs[c * 128];
        ull x0 = xr[mg], x1 = xr[mg + 32];
        const float* wr = &Wd[c * 64 + og * 8];
#pragma unroll
        for (int i = 0; i < 8; i++) {
            ull w = dup2(wr[i]);                       // ALU-pipe mov, overlaps FMA
            FMA2(acc[i][0], w, x0);
            FMA2(acc[i][1], w, x1);
        }
    }

#pragma unroll
    for (int i = 0; i < 8; i++) {
        int o = og * 8 + i;
        float bv = Bv[o];
#pragma unroll
        for (int j = 0; j < 2; j++) {
            float2 f = up2(acc[i][j]);
            f.x += bv; f.y += bv;
            *(float2*)&Y[(size_t)o * TV + m0 + (mg + 32 * j) * 2] = f;
        }
    }
}

// ---------------------------------------------------------------------------
// attn_part: split-K partial scores. Block (chunk, nh): 256 r's of the 2048.
// ---------------------------------------------------------------------------
__global__ __launch_bounds__(256) void attn_part()
{
    __shared__ float Qs[1600];
    __shared__ float Ks[1600];
    const int chunk = blockIdx.x;               // 0..7
    const int nh    = blockIdx.y;               // 0..255
    const float* Q = g_q + (size_t)nh * 102400 + chunk * 256 * 50;
    const float* K = g_k + (size_t)nh * 102400 + chunk * 256 * 50;
    const int tid = threadIdx.x;
    const bool active = tid < 250;
    const int v  = tid % 50;
    const int uq = tid / 50;

    float acc[10];
#pragma unroll
    for (int i = 0; i < 10; i++) acc[i] = 0.f;

    for (int kb = 0; kb < 256; kb += 32) {
        for (int idx = tid; idx < 1600; idx += 256) {
            Qs[idx] = Q[kb * 50 + idx];
            Ks[idx] = K[kb * 50 + idx];
        }
        __syncthreads();
        if (active) {
#pragma unroll 4
            for (int r = 0; r < 32; r++) {
                float kv = Ks[r * 50 + v];
#pragma unroll
                for (int i = 0; i < 10; i++)
                    acc[i] = fmaf(Qs[r * 50 + uq + 5 * i], kv, acc[i]);
            }
        }
        __syncthreads();
    }

    if (active) {
        float* P = g_part + (size_t)(nh * 8 + chunk) * 2500;
#pragma unroll
        for (int i = 0; i < 10; i++)
            P[(uq + 5 * i) * 50 + v] = acc[i];
    }
}

// ---------------------------------------------------------------------------
// attn_reduce: sum 8 partials, tanh * alpha + global_attn
// ---------------------------------------------------------------------------
__global__ __launch_bounds__(256) void attn_reduce(const float* __restrict__ alphas,
                                                   const float* __restrict__ ga)
{
    const int nh = blockIdx.x;
    const float alpha = alphas[nh & 7];
    const float* P = g_part + (size_t)nh * 8 * 2500;
    float* A = g_attn + (size_t)nh * 2500;
    for (int idx = threadIdx.x; idx < 2500; idx += 256) {
        float s = 0.f;
#pragma unroll
        for (int c = 0; c < 8; c++) s += P[c * 2500 + idx];
        A[idx] = tanhf(s * (1.0f / 2048.0f)) * alpha + ga[idx];
    }
}

// ---------------------------------------------------------------------------
// fused_out: per (n, t-tile of 2):
//   phase0: Vs = v_w @ x_kv_slab + v_b                       [64][128]
//   per h : Gs = o_w_h @ Vs ; out += Gs x attn_h
// SMEM strides padded (134 floats / 65 ulls) for conflict-free access.
// ---------------------------------------------------------------------------
#define GST 134                 // padded row stride (floats) for Xs/Gs/Vs
#define OFF_VS   0
#define OFF_XSGS (64 * GST)                 // floats
#define OFF_WD   (2 * 64 * GST)            // floats; Wd is ull[64][65]
#define OFF_AS   (2 * 64 * GST + 64 * 65 * 2)
#define FUSED_SMEM ((2 * 64 * GST + 64 * 65 * 2 + 50 * 64) * 4)

__device__ __forceinline__ void block_gemm(float* __restrict__ dst,
                                           const float* __restrict__ src,
                                           const ull* __restrict__ Wd2,
                                           const float* __restrict__ bias,
                                           int og, int vg)
{
    ull A[4][8];
#pragma unroll
    for (int i = 0; i < 4; i++)
#pragma unroll
        for (int j = 0; j < 8; j++) A[i][j] = 0ull;

#pragma unroll 2
    for (int c = 0; c < 64; c++) {
        ull w0 = Wd2[c * 65 + og * 4 + 0];
        ull w1 = Wd2[c * 65 + og * 4 + 1];
        ull w2 = Wd2[c * 65 + og * 4 + 2];
        ull w3 = Wd2[c * 65 + og * 4 + 3];
        const ull* xr = (const ull*)&src[c * GST];
#pragma unroll
        for (int j = 0; j < 8; j++) {
            ull x = xr[vg + 8 * j];
            FMA2(A[0][j], w0, x);
            FMA2(A[1][j], w1, x);
            FMA2(A[2][j], w2, x);
            FMA2(A[3][j], w3, x);
        }
    }
#pragma unroll
    for (int i = 0; i < 4; i++) {
        int r = og * 4 + i;
        float bv = bias ? bias[r] : 0.f;
#pragma unroll
        for (int j = 0; j < 8; j++) {
            float2 f = up2(A[i][j]);
            f.x += bv; f.y += bv;
            *(float2*)&dst[r * GST + (vg + 8 * j) * 2] = f;
        }
    }
}

__global__ __launch_bounds__(128, 2) void fused_out(const float* __restrict__ x_kv,
                                                    const float* __restrict__ v_w,
                                                    const float* __restrict__ v_b,
                                                    const float* __restrict__ o_w,
                                                    const float* __restrict__ o_b,
                                                    float* __restrict__ out)
{
    extern __shared__ float sm[];
    float* Vs   = sm + OFF_VS;      // [64][GST]
    float* XsGs = sm + OFF_XSGS;    // x_kv slab, later Gs
    ull*   Wd2  = (ull*)(sm + OFF_WD);   // [64][65] dup-packed weights
    float* As   = sm + OFF_AS;      // [50][64] attn, v-padded

    const int tb  = blockIdx.x;     // 0..127 (t-tiles of 2)
    const int n   = blockIdx.y;
    const int t0  = tb * 2;
    const int tid = threadIdx.x;
    const int og  = tid >> 3;       // 16 groups x 4 o
    const int vg  = tid & 7;        // 8 groups x 4 v-pairs

    // load x_kv slab: m = t*64 + u (u padded 50->64 with zeros)
    for (int idx = tid; idx < 8192; idx += 128) {
        int c = idx >> 7, m = idx & 127, t = m >> 6, u = m & 63;
        XsGs[c * GST + m] =
            (u < 50) ? x_kv[((size_t)(n * 64 + c) * 256 + t0 + t) * 50 + u] : 0.f;
    }
    // v_w dup-packed transposed
    for (int idx = tid; idx < 4096; idx += 128) {
        int c = idx & 63, o = idx >> 6;
        Wd2[c * 65 + o] = dup2(v_w[o * 64 + c]);
    }
    __syncthreads();

    // phase0: Vs = v_w @ Xs + v_b
    block_gemm(Vs, XsGs, Wd2, v_b, og, vg);

    ull B[2][4][4];
#pragma unroll
    for (int t = 0; t < 2; t++)
#pragma unroll
        for (int i = 0; i < 4; i++)
#pragma unroll
            for (int p = 0; p < 4; p++) B[t][i][p] = 0ull;

    for (int h = 0; h < 8; h++) {
        __syncthreads();   // prior phase B / phase0 done
        // o_w_h dup-packed transposed (c consecutive -> coalesced)
        for (int idx = tid; idx < 4096; idx += 128) {
            int c = idx & 63, o = idx >> 6;
            Wd2[c * 65 + o] = dup2(o_w[o * 512 + h * 64 + c]);
        }
        // attn tile, v-padded to 64
        {
            const float* A = g_attn + (size_t)(n * 8 + h) * 2500;
            for (int idx = tid; idx < 3200; idx += 128) {
                int u = idx >> 6, v = idx & 63;
                As[idx] = (v < 50) ? A[u * 50 + v] : 0.f;
            }
        }
        __syncthreads();

        // phase A: Gs = o_w_h @ Vs (overwrites Xs region)
        block_gemm(XsGs, Vs, Wd2, nullptr, og, vg);
        __syncthreads();

        // phase B: out += Gs x attn
#pragma unroll 2
        for (int u = 0; u < 50; u++) {
            const ull* ap = (const ull*)&As[u * 64 + vg * 8];
            ull a0 = ap[0], a1 = ap[1], a2 = ap[2], a3 = ap[3];
#pragma unroll
            for (int t = 0; t < 2; t++) {
#pragma unroll
                for (int i = 0; i < 4; i++) {
                    ull g = dup2(XsGs[(og * 4 + i) * GST + t * 64 + u]);
                    FMA2(B[t][i][0], g, a0);
                    FMA2(B[t][i][1], g, a1);
                    FMA2(B[t][i][2], g, a2);
                    FMA2(B[t][i][3], g, a3);
                }
            }
        }
    }

    // epilogue
#pragma unroll
    for (int t = 0; t < 2; t++) {
#pragma unroll
        for (int i = 0; i < 4; i++) {
            int o = og * 4 + i;
            float bv = o_b[o];
            float* op = out + ((size_t)(n * 64 + o) * 256 + t0 + t) * 50;
#pragma unroll
            for (int p = 0; p < 4; p++) {
                int v = vg * 8 + 2 * p;
                if (v < 50) {
                    float2 f = up2(B[t][i][p]);
                    f.x += bv; f.y += bv;
                    *(float2*)&op[v] = f;
                }
            }
        }
    }
}

// ---------------------------------------------------------------------------
extern "C" void kernel_launch(void* const* d_in, const int* in_sizes, int n_in,
                              void* d_out, int out_size)
{
    (void)in_sizes; (void)n_in; (void)out_size;
    const float* x_q    = (const float*)d_in[0];
    const float* x_kv   = (const float*)d_in[1];
    const float* q_w    = (const float*)d_in[2];
    const float* q_b    = (const float*)d_in[3];
    const float* k_w    = (const float*)d_in[4];
    const float* k_b    = (const float*)d_in[5];
    const float* v_w    = (const float*)d_in[6];
    const float* v_b    = (const float*)d_in[7];
    const float* o_w    = (const float*)d_in[8];
    const float* o_b    = (const float*)d_in[9];
    const float* alphas = (const float*)d_in[10];
    const float* ga     = (const float*)d_in[11];
    float* out = (float*)d_out;

    static bool attr_set = false;
    if (!attr_set) {
        cudaFuncSetAttribute(proj_qk, cudaFuncAttributeMaxDynamicSharedMemorySize, 49152);
        cudaFuncSetAttribute(fused_out, cudaFuncAttributeMaxDynamicSharedMemorySize, FUSED_SMEM);
        attr_set = true;
    }

    proj_qk<<<dim3(100, 32, 2), 256, 49152>>>(x_q, q_w, q_b, x_kv, k_w, k_b);
    attn_part<<<dim3(8, 256), 256>>>();
    attn_reduce<<<256, 256>>>(alphas, ga);
    fused_out<<<dim3(128, 32), 128, FUSED_SMEM>>>(x_kv, v_w, v_b, o_w, o_b, out);
}